// round 9
// baseline (speedup 1.0000x reference)
#include <cuda_runtime.h>
#include <cuda_bf16.h>
#include <cstdint>

// Problem constants (fixed by dataset): N=50000, E=800000, IN=OUT=128, fp32.
#define MAX_N 50176
#define FT    128

__device__ float g_emb[MAX_N * FT];     // aggregated neighbor features

// ---------------------------------------------------------------------------
// Packed fp32x2 helpers (sm_100+ SIMD fp32 — FFMA2 in SASS, 2x FFMA tput)
// ---------------------------------------------------------------------------
__device__ __forceinline__ unsigned long long fma2(unsigned long long a,
                                                   unsigned long long b,
                                                   unsigned long long c) {
    unsigned long long d;
    asm("fma.rn.f32x2 %0, %1, %2, %3;" : "=l"(d) : "l"(a), "l"(b), "l"(c));
    return d;
}
__device__ __forceinline__ unsigned long long pack2(float lo, float hi) {
    unsigned long long d;
    asm("mov.b64 %0, {%1, %2};" : "=l"(d) : "f"(lo), "f"(hi));
    return d;
}
__device__ __forceinline__ void unpack2(unsigned long long v, float& lo, float& hi) {
    asm("mov.b64 {%0, %1}, %2;" : "=f"(lo), "=f"(hi) : "l"(v));
}

// ---------------------------------------------------------------------------
// Kernel 1: weighted neighbor aggregation — ONE WARP PER NODE, fused CSR
// range discovery. Lanes 0/1 binary-search the SORTED edge_dst for
// lower_bound(n) / lower_bound(n+1) (L2-resident, hidden under warp
// parallelism), broadcast via shfl. Main loop: 8-way edge unroll keeps 8
// independent 512B x-row gathers in flight per warp (MLP≈8). Each lane owns
// 4 features (float4). No atomics, no block sync.
// ---------------------------------------------------------------------------
__global__ __launch_bounds__(256)
void agg_kernel(const float* __restrict__ x,
                const int* __restrict__ src,
                const int* __restrict__ dst,
                const float* __restrict__ wgt,
                float* __restrict__ emb, int Nn, int E) {
    int gw  = (blockIdx.x * blockDim.x + threadIdx.x) >> 5;   // warp = node
    if (gw >= Nn) return;
    int lid = threadIdx.x & 31;

    // fused row-pointer: lanes 0/1 search lower_bound(gw + lane)
    int lo = 0;
    if (lid < 2) {
        int target = gw + lid;
        int hi = E;
        while (lo < hi) {
            int mid = (lo + hi) >> 1;
            if (__ldg(&dst[mid]) < target) lo = mid + 1; else hi = mid;
        }
    }
    int start = __shfl_sync(0xffffffffu, lo, 0);
    int end   = __shfl_sync(0xffffffffu, lo, 1);

    float4 a0 = make_float4(0.f, 0.f, 0.f, 0.f);
    float4 a1 = a0, a2 = a0, a3 = a0;

    const float* xl = x + lid * 4;

    int e = start;
    int e8 = start + ((end - start) & ~7);
    for (; e < e8; e += 8) {
        int   s0 = __ldg(&src[e + 0]), s1 = __ldg(&src[e + 1]);
        int   s2 = __ldg(&src[e + 2]), s3 = __ldg(&src[e + 3]);
        int   s4 = __ldg(&src[e + 4]), s5 = __ldg(&src[e + 5]);
        int   s6 = __ldg(&src[e + 6]), s7 = __ldg(&src[e + 7]);
        float w0 = __ldg(&wgt[e + 0]), w1 = __ldg(&wgt[e + 1]);
        float w2 = __ldg(&wgt[e + 2]), w3 = __ldg(&wgt[e + 3]);
        float w4 = __ldg(&wgt[e + 4]), w5 = __ldg(&wgt[e + 5]);
        float w6 = __ldg(&wgt[e + 6]), w7 = __ldg(&wgt[e + 7]);
        float4 v0 = *reinterpret_cast<const float4*>(&xl[(size_t)s0 * FT]);
        float4 v1 = *reinterpret_cast<const float4*>(&xl[(size_t)s1 * FT]);
        float4 v2 = *reinterpret_cast<const float4*>(&xl[(size_t)s2 * FT]);
        float4 v3 = *reinterpret_cast<const float4*>(&xl[(size_t)s3 * FT]);
        float4 v4 = *reinterpret_cast<const float4*>(&xl[(size_t)s4 * FT]);
        float4 v5 = *reinterpret_cast<const float4*>(&xl[(size_t)s5 * FT]);
        float4 v6 = *reinterpret_cast<const float4*>(&xl[(size_t)s6 * FT]);
        float4 v7 = *reinterpret_cast<const float4*>(&xl[(size_t)s7 * FT]);
        a0.x = fmaf(w0, v0.x, a0.x); a0.y = fmaf(w0, v0.y, a0.y);
        a0.z = fmaf(w0, v0.z, a0.z); a0.w = fmaf(w0, v0.w, a0.w);
        a1.x = fmaf(w1, v1.x, a1.x); a1.y = fmaf(w1, v1.y, a1.y);
        a1.z = fmaf(w1, v1.z, a1.z); a1.w = fmaf(w1, v1.w, a1.w);
        a2.x = fmaf(w2, v2.x, a2.x); a2.y = fmaf(w2, v2.y, a2.y);
        a2.z = fmaf(w2, v2.z, a2.z); a2.w = fmaf(w2, v2.w, a2.w);
        a3.x = fmaf(w3, v3.x, a3.x); a3.y = fmaf(w3, v3.y, a3.y);
        a3.z = fmaf(w3, v3.z, a3.z); a3.w = fmaf(w3, v3.w, a3.w);
        a0.x = fmaf(w4, v4.x, a0.x); a0.y = fmaf(w4, v4.y, a0.y);
        a0.z = fmaf(w4, v4.z, a0.z); a0.w = fmaf(w4, v4.w, a0.w);
        a1.x = fmaf(w5, v5.x, a1.x); a1.y = fmaf(w5, v5.y, a1.y);
        a1.z = fmaf(w5, v5.z, a1.z); a1.w = fmaf(w5, v5.w, a1.w);
        a2.x = fmaf(w6, v6.x, a2.x); a2.y = fmaf(w6, v6.y, a2.y);
        a2.z = fmaf(w6, v6.z, a2.z); a2.w = fmaf(w6, v6.w, a2.w);
        a3.x = fmaf(w7, v7.x, a3.x); a3.y = fmaf(w7, v7.y, a3.y);
        a3.z = fmaf(w7, v7.z, a3.z); a3.w = fmaf(w7, v7.w, a3.w);
    }
    for (; e < end; e++) {
        int   s = __ldg(&src[e]);
        float w = __ldg(&wgt[e]);
        float4 v = *reinterpret_cast<const float4*>(&xl[(size_t)s * FT]);
        a0.x = fmaf(w, v.x, a0.x); a0.y = fmaf(w, v.y, a0.y);
        a0.z = fmaf(w, v.z, a0.z); a0.w = fmaf(w, v.w, a0.w);
    }

    float4 s;
    s.x = (a0.x + a1.x) + (a2.x + a3.x);
    s.y = (a0.y + a1.y) + (a2.y + a3.y);
    s.z = (a0.z + a1.z) + (a2.z + a3.z);
    s.w = (a0.w + a1.w) + (a2.w + a3.w);
    *reinterpret_cast<float4*>(&emb[(size_t)gw * FT + lid * 4]) = s;
}

// ---------------------------------------------------------------------------
// Kernel 2: out = relu([x | emb] @ W + bias), concat never materialized.
// BM=64, BN=128, BK=32 (8 k-tiles -> 16 barriers total, half of R5).
// 256 threads, 4x8 per-thread tile on PACKED fp32x2 (FFMA2). B pairs come
// straight out of LDS.128; A broadcast-packed once per row per kk.
// ---------------------------------------------------------------------------
#define BM 64
#define BN 128
#define BK 32
#define TM 4
#define TN 8

__global__ __launch_bounds__(256)
void gemm_kernel(const float* __restrict__ x,
                 const float* __restrict__ emb,
                 const float* __restrict__ W,     // [256, 128] row-major
                 const float* __restrict__ bias,  // [128]
                 float* __restrict__ out,
                 int M) {
    __shared__ __align__(16) float As[BK][BM];   // 8 KB (k-major)
    __shared__ __align__(16) float Bs[BK][BN];   // 16 KB

    const int tid = threadIdx.x;
    const int tx = tid & 15;        // 16 col groups of TN=8
    const int ty = tid >> 4;        // 16 row groups of TM=4
    const int block_row = blockIdx.x * BM;

    unsigned long long acc[TM][TN / 2];
    #pragma unroll
    for (int r = 0; r < TM; r++)
        #pragma unroll
        for (int j = 0; j < TN / 2; j++) acc[r][j] = 0ull;

    for (int k0 = 0; k0 < 2 * FT; k0 += BK) {
        // ---- load A tile: 64 rows x 32 k = 512 float4, 2 per thread ----
        #pragma unroll
        for (int j = 0; j < 2; j++) {
            int idx  = tid + j * 256;       // [0,512)
            int a_r  = idx >> 3;            // row in [0,64)
            int a_kq = (idx & 7) * 4;       // k offset in [0,32) step 4
            int grow = block_row + a_r;
            int gk   = k0 + a_kq;
            float4 v = make_float4(0.f, 0.f, 0.f, 0.f);
            if (grow < M) {
                const float* base = (gk < FT)
                    ? (x   + (size_t)grow * FT + gk)
                    : (emb + (size_t)grow * FT + (gk - FT));
                v = *reinterpret_cast<const float4*>(base);
            }
            As[a_kq + 0][a_r] = v.x;
            As[a_kq + 1][a_r] = v.y;
            As[a_kq + 2][a_r] = v.z;
            As[a_kq + 3][a_r] = v.w;
        }
        // ---- load B tile: 32 k x 128 = 1024 float4, 4 per thread ----
        #pragma unroll
        for (int j = 0; j < 4; j++) {
            int idx = tid + j * 256;        // [0,1024)
            int k   = idx >> 5;             // [0,32)
            int c4  = (idx & 31) * 4;       // [0,128) step 4
            float4 v = *reinterpret_cast<const float4*>(&W[(size_t)(k0 + k) * BN + c4]);
            *reinterpret_cast<float4*>(&Bs[k][c4]) = v;
        }
        __syncthreads();

        // ---- compute: packed fp32x2 outer product ----
        #pragma unroll
        for (int kk = 0; kk < BK; kk++) {
            float4 av = *reinterpret_cast<const float4*>(&As[kk][ty * TM]);
            ulonglong2 bp0 = *reinterpret_cast<const ulonglong2*>(&Bs[kk][tx * TN]);
            ulonglong2 bp1 = *reinterpret_cast<const ulonglong2*>(&Bs[kk][tx * TN + 4]);
            unsigned long long b[4] = {bp0.x, bp0.y, bp1.x, bp1.y};
            unsigned long long pa[TM];
            pa[0] = pack2(av.x, av.x);
            pa[1] = pack2(av.y, av.y);
            pa[2] = pack2(av.z, av.z);
            pa[3] = pack2(av.w, av.w);
            #pragma unroll
            for (int r = 0; r < TM; r++)
                #pragma unroll
                for (int j = 0; j < 4; j++)
                    acc[r][j] = fma2(pa[r], b[j], acc[r][j]);
        }
        __syncthreads();
    }

    // ---- epilogue: + bias, relu, float4 stores ----
    float4 bb0 = *reinterpret_cast<const float4*>(&bias[tx * TN]);
    float4 bb1 = *reinterpret_cast<const float4*>(&bias[tx * TN + 4]);
    float bv[TN] = {bb0.x, bb0.y, bb0.z, bb0.w, bb1.x, bb1.y, bb1.z, bb1.w};

    #pragma unroll
    for (int r = 0; r < TM; r++) {
        int grow = block_row + ty * TM + r;
        if (grow >= M) continue;
        float c[TN];
        #pragma unroll
        for (int j = 0; j < TN / 2; j++)
            unpack2(acc[r][j], c[2 * j], c[2 * j + 1]);
        float4 o0, o1;
        o0.x = fmaxf(c[0] + bv[0], 0.f);
        o0.y = fmaxf(c[1] + bv[1], 0.f);
        o0.z = fmaxf(c[2] + bv[2], 0.f);
        o0.w = fmaxf(c[3] + bv[3], 0.f);
        o1.x = fmaxf(c[4] + bv[4], 0.f);
        o1.y = fmaxf(c[5] + bv[5], 0.f);
        o1.z = fmaxf(c[6] + bv[6], 0.f);
        o1.w = fmaxf(c[7] + bv[7], 0.f);
        *reinterpret_cast<float4*>(&out[(size_t)grow * BN + tx * TN])     = o0;
        *reinterpret_cast<float4*>(&out[(size_t)grow * BN + tx * TN + 4]) = o1;
    }
}

// ---------------------------------------------------------------------------
// Launch. Inputs (metadata order):
//   0: x [N*128] f32, 1: edge_src [E] i32, 2: edge_dst [E] i32 (sorted),
//   3: edge_weight [E] f32, 4: weight [256*128] f32, 5: bias [128] f32
// ---------------------------------------------------------------------------
extern "C" void kernel_launch(void* const* d_in, const int* in_sizes, int n_in,
                              void* d_out, int out_size) {
    const float* x    = (const float*)d_in[0];
    const int*   esrc = (const int*)d_in[1];
    const int*   edst = (const int*)d_in[2];
    const float* ewgt = (const float*)d_in[3];
    const float* W    = (const float*)d_in[4];
    const float* bias = (const float*)d_in[5];
    float* out = (float*)d_out;

    int Nn = in_sizes[0] / FT;
    int E  = in_sizes[1];

    float* emb;
    cudaGetSymbolAddress((void**)&emb, g_emb);

    // warp-per-node aggregation (fused row-pointer discovery)
    agg_kernel<<<(Nn * 32 + 255) / 256, 256>>>(x, esrc, edst, ewgt, emb, Nn, E);
    gemm_kernel<<<(Nn + BM - 1) / BM, 256>>>(x, emb, W, bias, out, Nn);
}

// round 11
// speedup vs baseline: 1.4092x; 1.4092x over previous
#include <cuda_runtime.h>
#include <cuda_bf16.h>
#include <cstdint>

// Problem constants (fixed by dataset): N=50000, E=800000, IN=OUT=128, fp32.
#define MAX_N 50176
#define FT    128

__device__ float g_emb[MAX_N * FT];     // aggregated neighbor features

// ---------------------------------------------------------------------------
// Packed fp32x2 helpers (FFMA2 in SASS — 2x fp32 FMA throughput, bit-exact)
// ---------------------------------------------------------------------------
__device__ __forceinline__ unsigned long long fma2(unsigned long long a,
                                                   unsigned long long b,
                                                   unsigned long long c) {
    unsigned long long d;
    asm("fma.rn.f32x2 %0, %1, %2, %3;" : "=l"(d) : "l"(a), "l"(b), "l"(c));
    return d;
}
__device__ __forceinline__ unsigned long long pack2(float lo, float hi) {
    unsigned long long d;
    asm("mov.b64 %0, {%1, %2};" : "=l"(d) : "f"(lo), "f"(hi));
    return d;
}
__device__ __forceinline__ void unpack2(unsigned long long v, float& lo, float& hi) {
    asm("mov.b64 {%0, %1}, %2;" : "=f"(lo), "=f"(hi) : "l"(v));
}

// ---------------------------------------------------------------------------
// Kernel 1: weighted neighbor aggregation — ONE WARP PER NODE, fused CSR
// range discovery (lanes 0/1 binary-search sorted edge_dst, shfl broadcast).
// 8-way edge unroll => 8 independent 512B x-row gathers in flight per warp.
// Each lane owns 4 features (float4). No atomics, no block sync.
// ---------------------------------------------------------------------------
__global__ __launch_bounds__(256)
void agg_kernel(const float* __restrict__ x,
                const int* __restrict__ src,
                const int* __restrict__ dst,
                const float* __restrict__ wgt,
                float* __restrict__ emb, int Nn, int E) {
    int gw  = (blockIdx.x * blockDim.x + threadIdx.x) >> 5;   // warp = node
    if (gw >= Nn) return;
    int lid = threadIdx.x & 31;

    int lo = 0;
    if (lid < 2) {
        int target = gw + lid;
        int hi = E;
        while (lo < hi) {
            int mid = (lo + hi) >> 1;
            if (__ldg(&dst[mid]) < target) lo = mid + 1; else hi = mid;
        }
    }
    int start = __shfl_sync(0xffffffffu, lo, 0);
    int end   = __shfl_sync(0xffffffffu, lo, 1);

    float4 a0 = make_float4(0.f, 0.f, 0.f, 0.f);
    float4 a1 = a0, a2 = a0, a3 = a0;

    const float* xl = x + lid * 4;

    int e = start;
    int e8 = start + ((end - start) & ~7);
    for (; e < e8; e += 8) {
        int   s0 = __ldg(&src[e + 0]), s1 = __ldg(&src[e + 1]);
        int   s2 = __ldg(&src[e + 2]), s3 = __ldg(&src[e + 3]);
        int   s4 = __ldg(&src[e + 4]), s5 = __ldg(&src[e + 5]);
        int   s6 = __ldg(&src[e + 6]), s7 = __ldg(&src[e + 7]);
        float w0 = __ldg(&wgt[e + 0]), w1 = __ldg(&wgt[e + 1]);
        float w2 = __ldg(&wgt[e + 2]), w3 = __ldg(&wgt[e + 3]);
        float w4 = __ldg(&wgt[e + 4]), w5 = __ldg(&wgt[e + 5]);
        float w6 = __ldg(&wgt[e + 6]), w7 = __ldg(&wgt[e + 7]);
        float4 v0 = *reinterpret_cast<const float4*>(&xl[(size_t)s0 * FT]);
        float4 v1 = *reinterpret_cast<const float4*>(&xl[(size_t)s1 * FT]);
        float4 v2 = *reinterpret_cast<const float4*>(&xl[(size_t)s2 * FT]);
        float4 v3 = *reinterpret_cast<const float4*>(&xl[(size_t)s3 * FT]);
        float4 v4 = *reinterpret_cast<const float4*>(&xl[(size_t)s4 * FT]);
        float4 v5 = *reinterpret_cast<const float4*>(&xl[(size_t)s5 * FT]);
        float4 v6 = *reinterpret_cast<const float4*>(&xl[(size_t)s6 * FT]);
        float4 v7 = *reinterpret_cast<const float4*>(&xl[(size_t)s7 * FT]);
        a0.x = fmaf(w0, v0.x, a0.x); a0.y = fmaf(w0, v0.y, a0.y);
        a0.z = fmaf(w0, v0.z, a0.z); a0.w = fmaf(w0, v0.w, a0.w);
        a1.x = fmaf(w1, v1.x, a1.x); a1.y = fmaf(w1, v1.y, a1.y);
        a1.z = fmaf(w1, v1.z, a1.z); a1.w = fmaf(w1, v1.w, a1.w);
        a2.x = fmaf(w2, v2.x, a2.x); a2.y = fmaf(w2, v2.y, a2.y);
        a2.z = fmaf(w2, v2.z, a2.z); a2.w = fmaf(w2, v2.w, a2.w);
        a3.x = fmaf(w3, v3.x, a3.x); a3.y = fmaf(w3, v3.y, a3.y);
        a3.z = fmaf(w3, v3.z, a3.z); a3.w = fmaf(w3, v3.w, a3.w);
        a0.x = fmaf(w4, v4.x, a0.x); a0.y = fmaf(w4, v4.y, a0.y);
        a0.z = fmaf(w4, v4.z, a0.z); a0.w = fmaf(w4, v4.w, a0.w);
        a1.x = fmaf(w5, v5.x, a1.x); a1.y = fmaf(w5, v5.y, a1.y);
        a1.z = fmaf(w5, v5.z, a1.z); a1.w = fmaf(w5, v5.w, a1.w);
        a2.x = fmaf(w6, v6.x, a2.x); a2.y = fmaf(w6, v6.y, a2.y);
        a2.z = fmaf(w6, v6.z, a2.z); a2.w = fmaf(w6, v6.w, a2.w);
        a3.x = fmaf(w7, v7.x, a3.x); a3.y = fmaf(w7, v7.y, a3.y);
        a3.z = fmaf(w7, v7.z, a3.z); a3.w = fmaf(w7, v7.w, a3.w);
    }
    for (; e < end; e++) {
        int   s = __ldg(&src[e]);
        float w = __ldg(&wgt[e]);
        float4 v = *reinterpret_cast<const float4*>(&xl[(size_t)s * FT]);
        a0.x = fmaf(w, v.x, a0.x); a0.y = fmaf(w, v.y, a0.y);
        a0.z = fmaf(w, v.z, a0.z); a0.w = fmaf(w, v.w, a0.w);
    }

    float4 s;
    s.x = (a0.x + a1.x) + (a2.x + a3.x);
    s.y = (a0.y + a1.y) + (a2.y + a3.y);
    s.z = (a0.z + a1.z) + (a2.z + a3.z);
    s.w = (a0.w + a1.w) + (a2.w + a3.w);
    *reinterpret_cast<float4*>(&emb[(size_t)gw * FT + lid * 4]) = s;
}

// ---------------------------------------------------------------------------
// Kernel 2: out = relu([x | emb] @ W + bias), concat never materialized.
// BM=128, BN=128, BK=16, 256 threads, 8x8 per-thread tile on packed fp32x2.
// LDS bytes/FMA = 1.0 (was 1.5). Thread's 8 cols are split tx*4 and tx*4+64
// so B LDS.128 lane stride is 16B -> conflict-free banks. A reads are
// half-warp broadcasts. Each BK tile lies fully in x-half or emb-half.
// ---------------------------------------------------------------------------
#define BM 128
#define BN 128
#define BK 16
#define TM 8

__global__ __launch_bounds__(256, 2)
void gemm_kernel(const float* __restrict__ x,
                 const float* __restrict__ emb,
                 const float* __restrict__ W,     // [256, 128] row-major
                 const float* __restrict__ bias,  // [128]
                 float* __restrict__ out,
                 int M) {
    __shared__ __align__(16) float As[BK][BM];   // 8 KB (k-major)
    __shared__ __align__(16) float Bs[BK][BN];   // 8 KB

    const int tid = threadIdx.x;
    const int tx = tid & 15;        // 16 col groups (cols tx*4 .. and +64)
    const int ty = tid >> 4;        // 16 row groups of TM=8
    const int block_row = blockIdx.x * BM;

    // acc[r][j]: j=0,1 -> col pairs (tx*4 + 2j); j=2,3 -> (64 + tx*4 + 2(j-2))
    unsigned long long acc[TM][4];
    #pragma unroll
    for (int r = 0; r < TM; r++)
        #pragma unroll
        for (int j = 0; j < 4; j++) acc[r][j] = 0ull;

    // A-load mapping: idx in [0,512): row = idx>>2, kq = (idx&3)*4
    for (int k0 = 0; k0 < 2 * FT; k0 += BK) {
        const float* Asrc = (k0 < FT) ? x : emb;
        const int    kbase = (k0 < FT) ? k0 : (k0 - FT);
        #pragma unroll
        for (int j = 0; j < 2; j++) {
            int idx  = tid + j * 256;
            int a_r  = idx >> 2;            // [0,128)
            int a_kq = (idx & 3) * 4;       // [0,16) step 4
            int grow = block_row + a_r;
            float4 v = make_float4(0.f, 0.f, 0.f, 0.f);
            if (grow < M)
                v = *reinterpret_cast<const float4*>(
                        &Asrc[(size_t)grow * FT + kbase + a_kq]);
            As[a_kq + 0][a_r] = v.x;
            As[a_kq + 1][a_r] = v.y;
            As[a_kq + 2][a_r] = v.z;
            As[a_kq + 3][a_r] = v.w;
        }
        // B tile: 16 k x 128 cols = 512 float4, 2 per thread (coalesced, STS.128)
        #pragma unroll
        for (int j = 0; j < 2; j++) {
            int idx = tid + j * 256;        // [0,512)
            int k   = idx >> 5;             // [0,16)
            int c4  = (idx & 31) * 4;       // [0,128) step 4
            float4 v = *reinterpret_cast<const float4*>(&W[(size_t)(k0 + k) * BN + c4]);
            *reinterpret_cast<float4*>(&Bs[k][c4]) = v;
        }
        __syncthreads();

        #pragma unroll
        for (int kk = 0; kk < BK; kk++) {
            // A: 8 rows (broadcast within half-warp)
            float4 av0 = *reinterpret_cast<const float4*>(&As[kk][ty * TM]);
            float4 av1 = *reinterpret_cast<const float4*>(&As[kk][ty * TM + 4]);
            // B: two conflict-free 16B loads, 16B lane stride
            ulonglong2 bp0 = *reinterpret_cast<const ulonglong2*>(&Bs[kk][tx * 4]);
            ulonglong2 bp1 = *reinterpret_cast<const ulonglong2*>(&Bs[kk][tx * 4 + 64]);
            unsigned long long b[4] = {bp0.x, bp0.y, bp1.x, bp1.y};
            unsigned long long pa[TM];
            pa[0] = pack2(av0.x, av0.x);
            pa[1] = pack2(av0.y, av0.y);
            pa[2] = pack2(av0.z, av0.z);
            pa[3] = pack2(av0.w, av0.w);
            pa[4] = pack2(av1.x, av1.x);
            pa[5] = pack2(av1.y, av1.y);
            pa[6] = pack2(av1.z, av1.z);
            pa[7] = pack2(av1.w, av1.w);
            #pragma unroll
            for (int r = 0; r < TM; r++)
                #pragma unroll
                for (int j = 0; j < 4; j++)
                    acc[r][j] = fma2(pa[r], b[j], acc[r][j]);
        }
        __syncthreads();
    }

    // ---- epilogue: + bias, relu, two float4 stores per row ----
    float4 bb0 = *reinterpret_cast<const float4*>(&bias[tx * 4]);
    float4 bb1 = *reinterpret_cast<const float4*>(&bias[tx * 4 + 64]);

    #pragma unroll
    for (int r = 0; r < TM; r++) {
        int grow = block_row + ty * TM + r;
        if (grow >= M) continue;
        float c0, c1, c2, c3, c4, c5, c6, c7;
        unpack2(acc[r][0], c0, c1);
        unpack2(acc[r][1], c2, c3);
        unpack2(acc[r][2], c4, c5);
        unpack2(acc[r][3], c6, c7);
        float4 o0, o1;
        o0.x = fmaxf(c0 + bb0.x, 0.f);
        o0.y = fmaxf(c1 + bb0.y, 0.f);
        o0.z = fmaxf(c2 + bb0.z, 0.f);
        o0.w = fmaxf(c3 + bb0.w, 0.f);
        o1.x = fmaxf(c4 + bb1.x, 0.f);
        o1.y = fmaxf(c5 + bb1.y, 0.f);
        o1.z = fmaxf(c6 + bb1.z, 0.f);
        o1.w = fmaxf(c7 + bb1.w, 0.f);
        *reinterpret_cast<float4*>(&out[(size_t)grow * BN + tx * 4])      = o0;
        *reinterpret_cast<float4*>(&out[(size_t)grow * BN + tx * 4 + 64]) = o1;
    }
}

// ---------------------------------------------------------------------------
// Launch. Inputs (metadata order):
//   0: x [N*128] f32, 1: edge_src [E] i32, 2: edge_dst [E] i32 (sorted),
//   3: edge_weight [E] f32, 4: weight [256*128] f32, 5: bias [128] f32
// ---------------------------------------------------------------------------
extern "C" void kernel_launch(void* const* d_in, const int* in_sizes, int n_in,
                              void* d_out, int out_size) {
    const float* x    = (const float*)d_in[0];
    const int*   esrc = (const int*)d_in[1];
    const int*   edst = (const int*)d_in[2];
    const float* ewgt = (const float*)d_in[3];
    const float* W    = (const float*)d_in[4];
    const float* bias = (const float*)d_in[5];
    float* out = (float*)d_out;

    int Nn = in_sizes[0] / FT;
    int E  = in_sizes[1];

    float* emb;
    cudaGetSymbolAddress((void**)&emb, g_emb);

    agg_kernel<<<(Nn * 32 + 255) / 256, 256>>>(x, esrc, edst, ewgt, emb, Nn, E);
    gemm_kernel<<<(Nn + BM - 1) / BM, 256>>>(x, emb, W, bias, out, Nn);
}

// round 12
// speedup vs baseline: 1.5931x; 1.1305x over previous
#include <cuda_runtime.h>
#include <cuda_bf16.h>
#include <cstdint>

// Problem constants (fixed by dataset): N=50000, E=800000, IN=OUT=128, fp32.
#define FT        128
#define BM        128
#define BN        128
#define BK        16
#define EMB_PITCH 132   // 128 + 4 pad: 528B row pitch (16B-aligned, bank-skewed)

// smem layout (floats): emb_s[128*132] | As[16*128] | Bs[16*128] | rp[129] (ints)
#define SM_EMB   0
#define SM_AS    (BM * EMB_PITCH)
#define SM_BS    (SM_AS + BK * BM)
#define SM_RP    (SM_BS + BK * BN)
#define SMEM_FLOATS (SM_RP + 132)
#define SMEM_BYTES  (SMEM_FLOATS * 4)

// ---------------------------------------------------------------------------
// Packed fp32x2 helpers (FFMA2 in SASS — 2x fp32 FMA throughput, bit-exact)
// ---------------------------------------------------------------------------
__device__ __forceinline__ unsigned long long fma2(unsigned long long a,
                                                   unsigned long long b,
                                                   unsigned long long c) {
    unsigned long long d;
    asm("fma.rn.f32x2 %0, %1, %2, %3;" : "=l"(d) : "l"(a), "l"(b), "l"(c));
    return d;
}
__device__ __forceinline__ unsigned long long pack2(float lo, float hi) {
    unsigned long long d;
    asm("mov.b64 %0, {%1, %2};" : "=l"(d) : "f"(lo), "f"(hi));
    return d;
}
__device__ __forceinline__ void unpack2(unsigned long long v, float& lo, float& hi) {
    asm("mov.b64 {%0, %1}, %2;" : "=f"(lo), "=f"(hi) : "l"(v));
}

// ---------------------------------------------------------------------------
// FUSED kernel: per block of 128 rows —
//   phase 0: 129 parallel binary searches on sorted edge_dst -> block CSR
//   phase 1: warp-per-node aggregation into smem emb_s (no global emb!)
//   phase 2: relu([x | emb_s] @ W + bias) with the R11 8x8 FFMA2 GEMM;
//            emb-half A tiles staged from smem, x-half from global.
// Dependency is block-local, so gather (L2-bound) and GEMM (FMA-bound)
// phases of different blocks overlap on each SM (2 blocks/SM).
// ---------------------------------------------------------------------------
__global__ __launch_bounds__(256, 2)
void fused_kernel(const float* __restrict__ x,
                  const int* __restrict__ src,
                  const int* __restrict__ dst,
                  const float* __restrict__ wgt,
                  const float* __restrict__ W,     // [256,128] row-major
                  const float* __restrict__ bias,  // [128]
                  float* __restrict__ out,
                  int M, int E) {
    extern __shared__ float sm[];
    float* emb_s = sm + SM_EMB;
    float* As    = sm + SM_AS;     // k-major: As[kk*BM + row]
    float* Bs    = sm + SM_BS;     // Bs[kk*BN + col]
    int*   rp    = (int*)(sm + SM_RP);

    const int tid = threadIdx.x;
    const int block_row = blockIdx.x * BM;

    // ---- phase 0: block-local CSR row pointers (129 boundaries) ----
    if (tid <= BM) {
        int target = block_row + tid;
        int lo = 0, hi = E;
        while (lo < hi) {
            int mid = (lo + hi) >> 1;
            if (__ldg(&dst[mid]) < target) lo = mid + 1; else hi = mid;
        }
        rp[tid] = lo;
    }
    __syncthreads();

    // ---- phase 1: aggregation, warp per node, 16 nodes per warp ----
    {
        const int wid = tid >> 5;
        const int lid = tid & 31;
        const float* xl = x + lid * 4;
        #pragma unroll 1
        for (int t = 0; t < 16; t++) {
            int ln = wid * 16 + t;
            int start = rp[ln];
            int end   = rp[ln + 1];
            float4 a0 = make_float4(0.f, 0.f, 0.f, 0.f);
            float4 a1 = a0, a2 = a0, a3 = a0;
            int e = start;
            int e4 = start + ((end - start) & ~3);
            for (; e < e4; e += 4) {
                int   s0 = __ldg(&src[e + 0]), s1 = __ldg(&src[e + 1]);
                int   s2 = __ldg(&src[e + 2]), s3 = __ldg(&src[e + 3]);
                float w0 = __ldg(&wgt[e + 0]), w1 = __ldg(&wgt[e + 1]);
                float w2 = __ldg(&wgt[e + 2]), w3 = __ldg(&wgt[e + 3]);
                float4 v0 = *reinterpret_cast<const float4*>(&xl[(size_t)s0 * FT]);
                float4 v1 = *reinterpret_cast<const float4*>(&xl[(size_t)s1 * FT]);
                float4 v2 = *reinterpret_cast<const float4*>(&xl[(size_t)s2 * FT]);
                float4 v3 = *reinterpret_cast<const float4*>(&xl[(size_t)s3 * FT]);
                a0.x = fmaf(w0, v0.x, a0.x); a0.y = fmaf(w0, v0.y, a0.y);
                a0.z = fmaf(w0, v0.z, a0.z); a0.w = fmaf(w0, v0.w, a0.w);
                a1.x = fmaf(w1, v1.x, a1.x); a1.y = fmaf(w1, v1.y, a1.y);
                a1.z = fmaf(w1, v1.z, a1.z); a1.w = fmaf(w1, v1.w, a1.w);
                a2.x = fmaf(w2, v2.x, a2.x); a2.y = fmaf(w2, v2.y, a2.y);
                a2.z = fmaf(w2, v2.z, a2.z); a2.w = fmaf(w2, v2.w, a2.w);
                a3.x = fmaf(w3, v3.x, a3.x); a3.y = fmaf(w3, v3.y, a3.y);
                a3.z = fmaf(w3, v3.z, a3.z); a3.w = fmaf(w3, v3.w, a3.w);
            }
            for (; e < end; e++) {
                int   s = __ldg(&src[e]);
                float w = __ldg(&wgt[e]);
                float4 v = *reinterpret_cast<const float4*>(&xl[(size_t)s * FT]);
                a0.x = fmaf(w, v.x, a0.x); a0.y = fmaf(w, v.y, a0.y);
                a0.z = fmaf(w, v.z, a0.z); a0.w = fmaf(w, v.w, a0.w);
            }
            float4 r;
            r.x = (a0.x + a1.x) + (a2.x + a3.x);
            r.y = (a0.y + a1.y) + (a2.y + a3.y);
            r.z = (a0.z + a1.z) + (a2.z + a3.z);
            r.w = (a0.w + a1.w) + (a2.w + a3.w);
            *reinterpret_cast<float4*>(&emb_s[ln * EMB_PITCH + lid * 4]) = r;
        }
    }
    __syncthreads();

    // ---- phase 2: GEMM (R11 structure; emb half reads smem) ----
    const int tx = tid & 15;        // col groups: tx*4 and tx*4+64
    const int ty = tid >> 4;        // row groups of 8

    unsigned long long acc[8][4];
    #pragma unroll
    for (int r = 0; r < 8; r++)
        #pragma unroll
        for (int j = 0; j < 4; j++) acc[r][j] = 0ull;

    for (int k0 = 0; k0 < 2 * FT; k0 += BK) {
        const bool from_x = (k0 < FT);
        // A tile staging: 128 rows x 16 k = 512 float4, 2 per thread
        #pragma unroll
        for (int j = 0; j < 2; j++) {
            int idx  = tid + j * 256;
            int a_r  = idx >> 2;            // [0,128)
            int a_kq = (idx & 3) * 4;       // [0,16) step 4
            float4 v;
            if (from_x) {
                int grow = block_row + a_r;
                v = make_float4(0.f, 0.f, 0.f, 0.f);
                if (grow < M)
                    v = *reinterpret_cast<const float4*>(
                            &x[(size_t)grow * FT + k0 + a_kq]);
            } else {
                v = *reinterpret_cast<const float4*>(
                        &emb_s[a_r * EMB_PITCH + (k0 - FT) + a_kq]);
            }
            As[(a_kq + 0) * BM + a_r] = v.x;
            As[(a_kq + 1) * BM + a_r] = v.y;
            As[(a_kq + 2) * BM + a_r] = v.z;
            As[(a_kq + 3) * BM + a_r] = v.w;
        }
        // B tile: 16 k x 128 cols = 512 float4, 2 per thread
        #pragma unroll
        for (int j = 0; j < 2; j++) {
            int idx = tid + j * 256;
            int k   = idx >> 5;             // [0,16)
            int c4  = (idx & 31) * 4;       // [0,128) step 4
            float4 v = *reinterpret_cast<const float4*>(&W[(size_t)(k0 + k) * BN + c4]);
            *reinterpret_cast<float4*>(&Bs[k * BN + c4]) = v;
        }
        __syncthreads();

        #pragma unroll
        for (int kk = 0; kk < BK; kk++) {
            float4 av0 = *reinterpret_cast<const float4*>(&As[kk * BM + ty * 8]);
            float4 av1 = *reinterpret_cast<const float4*>(&As[kk * BM + ty * 8 + 4]);
            ulonglong2 bp0 = *reinterpret_cast<const ulonglong2*>(&Bs[kk * BN + tx * 4]);
            ulonglong2 bp1 = *reinterpret_cast<const ulonglong2*>(&Bs[kk * BN + tx * 4 + 64]);
            unsigned long long b[4] = {bp0.x, bp0.y, bp1.x, bp1.y};
            unsigned long long pa[8];
            pa[0] = pack2(av0.x, av0.x);
            pa[1] = pack2(av0.y, av0.y);
            pa[2] = pack2(av0.z, av0.z);
            pa[3] = pack2(av0.w, av0.w);
            pa[4] = pack2(av1.x, av1.x);
            pa[5] = pack2(av1.y, av1.y);
            pa[6] = pack2(av1.z, av1.z);
            pa[7] = pack2(av1.w, av1.w);
            #pragma unroll
            for (int r = 0; r < 8; r++)
                #pragma unroll
                for (int j = 0; j < 4; j++)
                    acc[r][j] = fma2(pa[r], b[j], acc[r][j]);
        }
        __syncthreads();
    }

    // ---- epilogue: + bias, relu, two float4 stores per row ----
    float4 bb0 = *reinterpret_cast<const float4*>(&bias[tx * 4]);
    float4 bb1 = *reinterpret_cast<const float4*>(&bias[tx * 4 + 64]);

    #pragma unroll
    for (int r = 0; r < 8; r++) {
        int grow = block_row + ty * 8 + r;
        if (grow >= M) continue;
        float c0, c1, c2, c3, c4, c5, c6, c7;
        unpack2(acc[r][0], c0, c1);
        unpack2(acc[r][1], c2, c3);
        unpack2(acc[r][2], c4, c5);
        unpack2(acc[r][3], c6, c7);
        float4 o0, o1;
        o0.x = fmaxf(c0 + bb0.x, 0.f);
        o0.y = fmaxf(c1 + bb0.y, 0.f);
        o0.z = fmaxf(c2 + bb0.z, 0.f);
        o0.w = fmaxf(c3 + bb0.w, 0.f);
        o1.x = fmaxf(c4 + bb1.x, 0.f);
        o1.y = fmaxf(c5 + bb1.y, 0.f);
        o1.z = fmaxf(c6 + bb1.z, 0.f);
        o1.w = fmaxf(c7 + bb1.w, 0.f);
        *reinterpret_cast<float4*>(&out[(size_t)grow * BN + tx * 4])      = o0;
        *reinterpret_cast<float4*>(&out[(size_t)grow * BN + tx * 4 + 64]) = o1;
    }
}

// ---------------------------------------------------------------------------
// Launch. Inputs (metadata order):
//   0: x [N*128] f32, 1: edge_src [E] i32, 2: edge_dst [E] i32 (sorted),
//   3: edge_weight [E] f32, 4: weight [256*128] f32, 5: bias [128] f32
// ---------------------------------------------------------------------------
extern "C" void kernel_launch(void* const* d_in, const int* in_sizes, int n_in,
                              void* d_out, int out_size) {
    const float* x    = (const float*)d_in[0];
    const int*   esrc = (const int*)d_in[1];
    const int*   edst = (const int*)d_in[2];
    const float* ewgt = (const float*)d_in[3];
    const float* W    = (const float*)d_in[4];
    const float* bias = (const float*)d_in[5];
    float* out = (float*)d_out;

    int Nn = in_sizes[0] / FT;
    int E  = in_sizes[1];

    static bool attr_set = false;
    if (!attr_set) {
        cudaFuncSetAttribute(fused_kernel,
                             cudaFuncAttributeMaxDynamicSharedMemorySize,
                             SMEM_BYTES);
        attr_set = true;
    }

    int grid = (Nn + BM - 1) / BM;
    fused_kernel<<<grid, 256, SMEM_BYTES>>>(x, esrc, edst, ewgt, W, bias,
                                            out, Nn, E);
}